// round 17
// baseline (speedup 1.0000x reference)
#include <cuda_runtime.h>
#include <math.h>
#include <float.h>

// Problem constants (fixed by the dataset):
//  B=1, N=8192 vertices, M=32*32*32=32768 grid points, Cin=32, Cout=64,
//  K=16 neighbors, edge_in=35 (32 feat + 3 rel_pos), Cprov=96 grid channels.
#define KNN_K   16
#define CIN     32
#define COUT    64
#define CPROV   96
#define MAXM    32768
#define MAXN    8192
#define SCALE   32.0f   // RES / (aabb_max - aabb_min), uniform

#define NB      16      // bins per axis
#define NCELLS  (NB*NB*NB)

__device__ int    g_knn[MAXM * KNN_K];
__device__ int    g_cnt[NCELLS];
__device__ int    g_start[NCELLS + 1];
__device__ int    g_cursor[NCELLS];
__device__ float4 g_pts[MAXN];        // scaled (x,y,z,|p|^2), binned order
__device__ int    g_idx[MAXN];        // original vertex index, binned order
__device__ float  g_F1[MAXN * COUT];  // feats@ew1[0:32] + eb1  (per vertex)
__device__ float4 g_aux[2 * MAXN];    // per-vertex LN stats + position:
                                      //  [2n]   = (S1, Q0, Qx, Qy)
                                      //  [2n+1] = (Qz, px, py, pz)
__device__ float  g_tab[3 * 32 * COUT]; // per-axis grid-feature @ ow1[64:160]

__device__ __forceinline__ int cell_of(float x, float y, float z) {
    int cx = min(NB - 1, max(0, (int)(x * (float)NB)));
    int cy = min(NB - 1, max(0, (int)(y * (float)NB)));
    int cz = min(NB - 1, max(0, (int)(z * (float)NB)));
    return (cx << 8) | (cy << 4) | cz;
}

// ---------------------------------------------------------------------------
// Binning: count -> scan -> scatter (scatter re-zeroes g_cnt for next replay).
// ---------------------------------------------------------------------------
__global__ void count_kernel(const float* __restrict__ verts, int N) {
    int n = blockIdx.x * blockDim.x + threadIdx.x;
    if (n < N) {
        int c = cell_of(verts[3*n], verts[3*n+1], verts[3*n+2]);
        atomicAdd(&g_cnt[c], 1);
    }
}

__global__ __launch_bounds__(1024) void scan_kernel() {
    __shared__ int s[1024];
    int t = threadIdx.x;
    int base = t * 4;
    int c0 = g_cnt[base], c1 = g_cnt[base+1], c2 = g_cnt[base+2], c3 = g_cnt[base+3];
    int tot = c0 + c1 + c2 + c3;
    s[t] = tot;
    __syncthreads();
    for (int off = 1; off < 1024; off <<= 1) {
        int v = s[t];
        if (t >= off) v += s[t - off];
        __syncthreads();
        s[t] = v;
        __syncthreads();
    }
    int excl = s[t] - tot;
    int p0 = excl, p1 = excl + c0, p2 = p1 + c1, p3 = p2 + c2;
    g_start[base]   = p0; g_cursor[base]   = p0;
    g_start[base+1] = p1; g_cursor[base+1] = p1;
    g_start[base+2] = p2; g_cursor[base+2] = p2;
    g_start[base+3] = p3; g_cursor[base+3] = p3;
    if (t == 1023) g_start[NCELLS] = s[1023];
}

__global__ void scatter_kernel(const float* __restrict__ verts, int N) {
    int n = blockIdx.x * blockDim.x + threadIdx.x;
    if (n < NCELLS) g_cnt[n] = 0;   // reset for next replay (g_cnt dead here)
    if (n < N) {
        float x = verts[3*n], y = verts[3*n+1], z = verts[3*n+2];
        int c = cell_of(x, y, z);
        int pos = atomicAdd(&g_cursor[c], 1);
        float sx = x * SCALE, sy = y * SCALE, sz = z * SCALE;
        g_pts[pos] = make_float4(sx, sy, sz, sx*sx + sy*sy + sz*sz);
        g_idx[pos] = n;
    }
}

// ---------------------------------------------------------------------------
// Binned exact KNN, 8 lanes per grid point (occupancy was grid-limited at
// 35% with 4 lanes/point; 8192 warps lifts the issue-slot ceiling and
// halves per-lane serial scan work).
//  - lane&7 = candidate share (i += 8 strided)
//  - per-lane DISTANCE-ONLY sorted top-16 (branch-guarded min/max insertion)
//  - shell stop: count of candidates <= (2r)^2 across the 8-lane group >= 16
//  - 3-stage bitonic merge of 8 sorted lists -> exact 16th-smallest T
//  - pass B: rescan same shells, emit indices with d2 <= T
//  - warp covers 2x2x1 points; block covers 4x4x2 -> coherent shell walks
// ---------------------------------------------------------------------------
__global__ __launch_bounds__(256) void knn_binned_kernel(
    const float* __restrict__ gverts, int M)
{
    __shared__ int ss[NCELLS + 1];
    __shared__ int scnt[32];
    for (int i = threadIdx.x; i < NCELLS + 1; i += 256) ss[i] = g_start[i];
    if (threadIdx.x < 32) scnt[threadIdx.x] = 0;
    __syncthreads();

    int b  = blockIdx.x;                       // 1024 blocks = 8x8x16
    int bx = b & 7, by = (b >> 3) & 7, bz = b >> 6;
    int w  = threadIdx.x >> 5;                 // 8 warps, each 2x2x1 points
    int lane = threadIdx.x & 31;
    int q  = lane >> 3, sub = lane & 7;        // point-in-warp, share
    int ix = bx*4 + (w & 1)*2        + (q & 1);
    int iy = by*4 + ((w >> 1) & 1)*2 + (q >> 1);
    int iz = bz*2 + (w >> 2);
    int m  = (ix << 10) | (iy << 5) | iz;
    if (m >= M) return;
    unsigned gmask = 0xFFu << (lane & 24);     // 8-lane group mask
    int pidx = threadIdx.x >> 3;               // per-block point index (0..31)

    float gx = gverts[3*m+0], gy = gverts[3*m+1], gz = gverts[3*m+2];
    float qx = gx * SCALE, qy = gy * SCALE, qz = gz * SCALE;
    float qq  = qx*qx + qy*qy + qz*qz;
    float m2x = -2.f*qx, m2y = -2.f*qy, m2z = -2.f*qz;

    int qcx = min(NB-1, max(0, (int)(gx * (float)NB)));
    int qcy = min(NB-1, max(0, (int)(gy * (float)NB)));
    int qcz = min(NB-1, max(0, (int)(gz * (float)NB)));

    float bv[KNN_K];
#pragma unroll
    for (int j = 0; j < KNN_K; j++) bv[j] = FLT_MAX;

    // enumerate the contiguous candidate spans of Chebyshev shell r
    auto shell_spans = [&](int r, auto&& fn) {
        int x0 = max(qcx - r, 0), x1 = min(qcx + r, NB - 1);
        int y0 = max(qcy - r, 0), y1 = min(qcy + r, NB - 1);
        int z0 = max(qcz - r, 0), z1 = min(qcz + r, NB - 1);
        for (int cx = x0; cx <= x1; cx++) {
            bool fx = (cx == qcx - r) || (cx == qcx + r);
            for (int cy = y0; cy <= y1; cy++) {
                bool fxy = fx || (cy == qcy - r) || (cy == qcy + r);
                int cbase = (cx << 8) | (cy << 4);
                if (fxy) {
                    fn(ss[cbase | z0], ss[(cbase | z1) + 1]);
                } else {
                    if (qcz - r >= 0) {
                        int c = cbase | (qcz - r);
                        fn(ss[c], ss[c + 1]);
                    }
                    if (r > 0 && qcz + r <= NB - 1) {
                        int c = cbase | (qcz + r);
                        fn(ss[c], ss[c + 1]);
                    }
                }
            }
        }
    };

    // ---- pass A: distances only ----
    auto scanA = [&](int s, int e) {
        for (int i = s + sub; i < e; i += 8) {
            float4 v = g_pts[i];
            float d2 = fmaf(m2x, v.x, fmaf(m2y, v.y, fmaf(m2z, v.z, qq + v.w)));
            if (d2 < bv[15]) {              // sorted insertion (asc)
                float vv = d2;
#pragma unroll
                for (int j = 0; j < KNN_K; j++) {
                    float lo = fminf(bv[j], vv);
                    vv = fmaxf(bv[j], vv);
                    bv[j] = lo;
                }
            }
        }
    };

    int rstop = NB - 1;
    for (int r = 0; r < NB; r++) {
        shell_spans(r, scanA);
        float bound2 = (float)(4 * r * r);
        int c = 0;
#pragma unroll
        for (int j = 0; j < KNN_K; j++) c += (bv[j] <= bound2) ? 1 : 0;
        c += __shfl_xor_sync(gmask, c, 1);
        c += __shfl_xor_sync(gmask, c, 2);
        c += __shfl_xor_sync(gmask, c, 4);
        if (c >= KNN_K) { rstop = r; break; }
    }

    // ---- bitonic merge of 8 sorted lists (xor 1, 2, 4) ----
#pragma unroll
    for (int stage = 1; stage <= 4; stage <<= 1) {
        float pb[KNN_K];
#pragma unroll
        for (int j = 0; j < KNN_K; j++)
            pb[j] = __shfl_xor_sync(gmask, bv[15 - j], stage);
#pragma unroll
        for (int j = 0; j < KNN_K; j++) bv[j] = fminf(bv[j], pb[j]);  // bitonic low half
#pragma unroll
        for (int s = 8; s >= 1; s >>= 1) {
#pragma unroll
            for (int j = 0; j < KNN_K; j++) {
                if ((j & s) == 0) {
                    float lo = fminf(bv[j], bv[j + s]);
                    bv[j + s] = fmaxf(bv[j], bv[j + s]);
                    bv[j] = lo;
                }
            }
        }
    }
    float T = bv[15];   // exact 16th-smallest distance (identical in all 8 lanes)

    // ---- pass B: recover identities ----
    auto scanB = [&](int s, int e) {
        for (int i = s + sub; i < e; i += 8) {
            float4 v = g_pts[i];
            float d2 = fmaf(m2x, v.x, fmaf(m2y, v.y, fmaf(m2z, v.z, qq + v.w)));
            if (d2 <= T) {
                int slot = atomicAdd(&scnt[pidx], 1);
                if (slot < KNN_K) g_knn[m*KNN_K + slot] = g_idx[i];
            }
        }
    };
    for (int r = 0; r <= rstop; r++) shell_spans(r, scanB);
}

// ---------------------------------------------------------------------------
// Fused precompute kernel.
//  Blocks [0,1024):  F1[n] = feats[n]@ew1[0:32] + eb1 per vertex, PLUS the
//    per-vertex LN statistics (S1, Q0, Qx, Qy, Qz) and position in g_aux.
//  Blocks [1024,1036): per-axis tables of gfeat@ow1[64:160] (exact separable
//    split: channel block 32a depends only on axis-a coordinate).
// ---------------------------------------------------------------------------
__global__ __launch_bounds__(256) void f1tab_kernel(
    const float* __restrict__ feats, const float* __restrict__ verts,
    const float* __restrict__ ew1,   const float* __restrict__ eb1,
    const float* __restrict__ gfeat, const float* __restrict__ ow1, int N)
{
    int w = threadIdx.x >> 5, lane = threadIdx.x & 31;
    if (blockIdx.x < 1024) {
        int n = blockIdx.x * 8 + w;
        if (n >= N) return;
        float fl = feats[n*CIN + lane];
        float2 b = ((const float2*)eb1)[lane];
        float a0 = b.x, a1 = b.y;
        const float2* w1 = (const float2*)ew1;
#pragma unroll
        for (int j = 0; j < CIN; j++) {
            float fv = __shfl_sync(0xffffffffu, fl, j);
            float2 wv = w1[j*32 + lane];
            a0 = fmaf(fv, wv.x, a0);
            a1 = fmaf(fv, wv.y, a1);
        }
        ((float2*)g_F1)[n*32 + lane] = make_float2(a0, a1);

        float2 wpx = w1[32*32 + lane];
        float2 wpy = w1[33*32 + lane];
        float2 wpz = w1[34*32 + lane];
        float s1 = a0 + a1;
        float q0 = a0*a0 + a1*a1;
        float qx = a0*wpx.x + a1*wpx.y;
        float qy = a0*wpy.x + a1*wpy.y;
        float qz = a0*wpz.x + a1*wpz.y;
#pragma unroll
        for (int o = 16; o; o >>= 1) {
            s1 += __shfl_xor_sync(0xffffffffu, s1, o);
            q0 += __shfl_xor_sync(0xffffffffu, q0, o);
            qx += __shfl_xor_sync(0xffffffffu, qx, o);
            qy += __shfl_xor_sync(0xffffffffu, qy, o);
            qz += __shfl_xor_sync(0xffffffffu, qz, o);
        }
        if (lane == 0) {
            g_aux[2*n]   = make_float4(s1, q0, qx, qy);
            g_aux[2*n+1] = make_float4(qz, verts[3*n], verts[3*n+1], verts[3*n+2]);
        }
    } else {
        int row = (blockIdx.x - 1024) * 8 + w;          // 0..95
        if (row >= 96) return;
        int a = row >> 5, i = row & 31;
        int m_sel = (a == 0) ? (i << 10) : ((a == 1) ? (i << 5) : i);
        const float* gf = gfeat + m_sel * CPROV + 32 * a;
        const float2* wo = (const float2*)(ow1 + (COUT + 32 * a) * COUT);
        float t0 = 0.f, t1 = 0.f;
#pragma unroll
        for (int j = 0; j < 32; j++) {
            float gv = gf[j];
            float2 wv = wo[j*32 + lane];
            t0 = fmaf(gv, wv.x, t0);
            t1 = fmaf(gv, wv.y, t1);
        }
        ((float2*)g_tab)[row*32 + lane] = make_float2(t0, t1);
    }
}

// ---------------------------------------------------------------------------
// Fused MLP. One warp per 4 grid points. Phase-1 LayerNorm statistics from
// the algebraic decomposition (no warp reductions in the k-loop).
// ---------------------------------------------------------------------------
__device__ __forceinline__ float gelu_fast(float x) {
    float x3 = x * x * x;
    float g = 1.5957691216057308f * fmaf(0.044715f, x3, x);   // 2*0.79788456*(...)
    float e = __expf(g);
    float t = 1.0f - __fdividef(2.0f, e + 1.0f);              // = tanh(g/2)
    return 0.5f * x * (1.0f + t);
}

#define GPW 4   // grid points per warp
#define WPB 8   // warps per block
__global__ __launch_bounds__(WPB*32) void mlp_kernel(
    const float* __restrict__ gverts, const float* __restrict__ ew1,
    const float* __restrict__ eg1,  const float* __restrict__ ebt1,
    const float* __restrict__ ew2,  const float* __restrict__ eb2,
    const float* __restrict__ ow1,  const float* __restrict__ ob1,
    const float* __restrict__ og1,  const float* __restrict__ obt1,
    const float* __restrict__ ow2,  const float* __restrict__ ob2,
    float* __restrict__ out, int M)
{
    __shared__ __align__(16) float sh_a[WPB][GPW][COUT];  // staging A
    __shared__ __align__(16) float sh_b[WPB][GPW][COUT];  // staging B

    int w = threadIdx.x >> 5, lane = threadIdx.x & 31;
    int mbase = (blockIdx.x * WPB + w) * GPW;
    if (mbase >= M) return;   // uniform per warp

    float2 wpx = ((const float2*)ew1)[32*32 + lane];
    float2 wpy = ((const float2*)ew1)[33*32 + lane];
    float2 wpz = ((const float2*)ew1)[34*32 + lane];
    float2 ge1 = ((const float2*)eg1)[lane];
    float2 bt1 = ((const float2*)ebt1)[lane];
    const float2* F1 = (const float2*)g_F1;

    // global weight moments (uniform across warp after reduction)
    float SWX = wpx.x + wpx.y, SWY = wpy.x + wpy.y, SWZ = wpz.x + wpz.y;
    float WXX = wpx.x*wpx.x + wpx.y*wpx.y;
    float WYY = wpy.x*wpy.x + wpy.y*wpy.y;
    float WZZ = wpz.x*wpz.x + wpz.y*wpz.y;
    float WXY = wpx.x*wpy.x + wpx.y*wpy.y;
    float WXZ = wpx.x*wpz.x + wpx.y*wpz.y;
    float WYZ = wpy.x*wpz.x + wpy.y*wpz.y;
#pragma unroll
    for (int o = 16; o; o >>= 1) {
        SWX += __shfl_xor_sync(0xffffffffu, SWX, o);
        SWY += __shfl_xor_sync(0xffffffffu, SWY, o);
        SWZ += __shfl_xor_sync(0xffffffffu, SWZ, o);
        WXX += __shfl_xor_sync(0xffffffffu, WXX, o);
        WYY += __shfl_xor_sync(0xffffffffu, WYY, o);
        WZZ += __shfl_xor_sync(0xffffffffu, WZZ, o);
        WXY += __shfl_xor_sync(0xffffffffu, WXY, o);
        WXZ += __shfl_xor_sync(0xffffffffu, WXZ, o);
        WYZ += __shfl_xor_sync(0xffffffffu, WYZ, o);
    }

    // ---- phase 1: per point, edge layer1 + LN + GELU + mean over K ----
#pragma unroll
    for (int p = 0; p < GPW; p++) {
        int m = mbase + p;
        float gx = gverts[3*m+0], gy = gverts[3*m+1], gz = gverts[3*m+2];
        int myn = 0;
        if (lane < KNN_K) myn = g_knn[m*KNN_K + lane];
        float gm0 = 0.f, gm1 = 0.f;
#pragma unroll
        for (int k = 0; k < KNN_K; k++) {
            int n = __shfl_sync(0xffffffffu, myn, k);
            float4 A = g_aux[2*n];        // (S1, Q0, Qx, Qy)  broadcast
            float4 B = g_aux[2*n+1];      // (Qz, px, py, pz)  broadcast
            float rx = B.y - gx, ry = B.z - gy, rz = B.w - gz;
            float s  = A.x + rx*SWX + ry*SWY + rz*SWZ;
            float s2 = A.y + 2.f*(rx*A.z + ry*A.w + rz*B.x)
                     + rx*rx*WXX + ry*ry*WYY + rz*rz*WZZ
                     + 2.f*(rx*ry*WXY + rx*rz*WXZ + ry*rz*WYZ);
            float mean = s * (1.f/COUT);
            float inv  = rsqrtf(s2 * (1.f/COUT) - mean*mean + 1e-5f);
            float2 f = F1[n*32 + lane];
            float a0 = fmaf(rx, wpx.x, fmaf(ry, wpy.x, fmaf(rz, wpz.x, f.x)));
            float a1 = fmaf(rx, wpx.y, fmaf(ry, wpy.y, fmaf(rz, wpz.y, f.y)));
            a0 = (a0 - mean) * inv * ge1.x + bt1.x;
            a1 = (a1 - mean) * inv * ge1.y + bt1.y;
            gm0 += gelu_fast(a0);
            gm1 += gelu_fast(a1);
        }
        *(float2*)&sh_a[w][p][2*lane] = make_float2(gm0 * (1.f/KNN_K), gm1 * (1.f/KNN_K));
    }
    __syncwarp();

    // ---- phase 2: edge layer 2 (hoisted past mean): 64 -> 64, x4 points ----
    {
        float2 be2 = ((const float2*)eb2)[lane];
        float a0[GPW], a1[GPW];
#pragma unroll
        for (int p = 0; p < GPW; p++) { a0[p] = be2.x; a1[p] = be2.y; }
        const float2* w2 = (const float2*)ew2;
#pragma unroll
        for (int i4 = 0; i4 < 16; i4++) {
            float2 wa = w2[(4*i4+0)*32 + lane];
            float2 wb = w2[(4*i4+1)*32 + lane];
            float2 wc = w2[(4*i4+2)*32 + lane];
            float2 wd = w2[(4*i4+3)*32 + lane];
#pragma unroll
            for (int p = 0; p < GPW; p++) {
                float4 v = ((const float4*)sh_a[w][p])[i4];
                a0[p] = fmaf(v.x, wa.x, a0[p]); a1[p] = fmaf(v.x, wa.y, a1[p]);
                a0[p] = fmaf(v.y, wb.x, a0[p]); a1[p] = fmaf(v.y, wb.y, a1[p]);
                a0[p] = fmaf(v.z, wc.x, a0[p]); a1[p] = fmaf(v.z, wc.y, a1[p]);
                a0[p] = fmaf(v.w, wd.x, a0[p]); a1[p] = fmaf(v.w, wd.y, a1[p]);
            }
        }
        __syncwarp();
#pragma unroll
        for (int p = 0; p < GPW; p++)
            *(float2*)&sh_b[w][p][2*lane] = make_float2(a0[p], a1[p]);
        __syncwarp();
    }

    // ---- phase 3: out layer 1: agg(64)@ow1[0:64] + table(ix,iy,iz), LN, GELU ----
    {
        float2 bo1 = ((const float2*)ob1)[lane];
        float c0[GPW], c1[GPW];
#pragma unroll
        for (int p = 0; p < GPW; p++) { c0[p] = bo1.x; c1[p] = bo1.y; }
        const float2* wo1 = (const float2*)ow1;
#pragma unroll
        for (int i4 = 0; i4 < 16; i4++) {
            float2 wa = wo1[(4*i4+0)*32 + lane];
            float2 wb = wo1[(4*i4+1)*32 + lane];
            float2 wc = wo1[(4*i4+2)*32 + lane];
            float2 wd = wo1[(4*i4+3)*32 + lane];
#pragma unroll
            for (int p = 0; p < GPW; p++) {
                float4 v = ((const float4*)sh_b[w][p])[i4];
                c0[p] = fmaf(v.x, wa.x, c0[p]); c1[p] = fmaf(v.x, wa.y, c1[p]);
                c0[p] = fmaf(v.y, wb.x, c0[p]); c1[p] = fmaf(v.y, wb.y, c1[p]);
                c0[p] = fmaf(v.z, wc.x, c0[p]); c1[p] = fmaf(v.z, wc.y, c1[p]);
                c0[p] = fmaf(v.w, wd.x, c0[p]); c1[p] = fmaf(v.w, wd.y, c1[p]);
            }
        }
        const float2* tab = (const float2*)g_tab;
        float2 go = ((const float2*)og1)[lane];
        float2 bo = ((const float2*)obt1)[lane];
#pragma unroll
        for (int p = 0; p < GPW; p++) {
            int m = mbase + p;
            int ix = m >> 10, iy = (m >> 5) & 31, iz = m & 31;
            float2 tx = tab[(0*32 + ix)*32 + lane];
            float2 ty = tab[(1*32 + iy)*32 + lane];
            float2 tz = tab[(2*32 + iz)*32 + lane];
            float a0 = c0[p] + tx.x + ty.x + tz.x;
            float a1 = c1[p] + tx.y + ty.y + tz.y;
            float s = a0 + a1, s2 = a0*a0 + a1*a1;
#pragma unroll
            for (int o = 16; o; o >>= 1) {
                s  += __shfl_xor_sync(0xffffffffu, s,  o);
                s2 += __shfl_xor_sync(0xffffffffu, s2, o);
            }
            float mean = s * (1.f/COUT);
            float inv  = rsqrtf(s2 * (1.f/COUT) - mean*mean + 1e-5f);
            a0 = (a0 - mean) * inv * go.x + bo.x;
            a1 = (a1 - mean) * inv * go.y + bo.y;
            *(float2*)&sh_a[w][p][2*lane] = make_float2(gelu_fast(a0), gelu_fast(a1));
        }
        __syncwarp();
    }

    // ---- phase 4: out layer 2: 64 -> 64, x4 points, store ----
    {
        float2 bo2 = ((const float2*)ob2)[lane];
        float o0[GPW], o1[GPW];
#pragma unroll
        for (int p = 0; p < GPW; p++) { o0[p] = bo2.x; o1[p] = bo2.y; }
        const float2* wo2 = (const float2*)ow2;
#pragma unroll
        for (int i4 = 0; i4 < 16; i4++) {
            float2 wa = wo2[(4*i4+0)*32 + lane];
            float2 wb = wo2[(4*i4+1)*32 + lane];
            float2 wc = wo2[(4*i4+2)*32 + lane];
            float2 wd = wo2[(4*i4+3)*32 + lane];
#pragma unroll
            for (int p = 0; p < GPW; p++) {
                float4 v = ((const float4*)sh_a[w][p])[i4];
                o0[p] = fmaf(v.x, wa.x, o0[p]); o1[p] = fmaf(v.x, wa.y, o1[p]);
                o0[p] = fmaf(v.y, wb.x, o0[p]); o1[p] = fmaf(v.y, wb.y, o1[p]);
                o0[p] = fmaf(v.z, wc.x, o0[p]); o1[p] = fmaf(v.z, wc.y, o1[p]);
                o0[p] = fmaf(v.w, wd.x, o0[p]); o1[p] = fmaf(v.w, wd.y, o1[p]);
            }
        }
#pragma unroll
        for (int p = 0; p < GPW; p++)
            ((float2*)out)[(mbase + p)*32 + lane] = make_float2(o0[p], o1[p]);
    }
}

// ---------------------------------------------------------------------------
// Launch. Input order:
//  0 vertices (1,N,3)  1 features (1,N,32)  2 grid_verts (M,3)  3 grid_feat (M,96)
//  4 ew1 (35,64) 5 eb1 6 eg1 7 ebt1 8 ew2 (64,64) 9 eb2
//  10 ow1 (160,64) 11 ob1 12 og1 13 obt1 14 ow2 (64,64) 15 ob2
// Output: (1,32,32,32,64) float32.
// ---------------------------------------------------------------------------
extern "C" void kernel_launch(void* const* d_in, const int* in_sizes, int n_in,
                              void* d_out, int out_size)
{
    const float* verts  = (const float*)d_in[0];
    const float* feats  = (const float*)d_in[1];
    const float* gverts = (const float*)d_in[2];
    const float* gfeat  = (const float*)d_in[3];
    const float* ew1  = (const float*)d_in[4];
    const float* eb1  = (const float*)d_in[5];
    const float* eg1  = (const float*)d_in[6];
    const float* ebt1 = (const float*)d_in[7];
    const float* ew2  = (const float*)d_in[8];
    const float* eb2  = (const float*)d_in[9];
    const float* ow1  = (const float*)d_in[10];
    const float* ob1  = (const float*)d_in[11];
    const float* og1  = (const float*)d_in[12];
    const float* obt1 = (const float*)d_in[13];
    const float* ow2  = (const float*)d_in[14];
    const float* ob2  = (const float*)d_in[15];

    int N = in_sizes[0] / 3;
    int M = in_sizes[2] / 3;

    count_kernel<<<(N + 255) / 256, 256>>>(verts, N);
    scan_kernel<<<1, 1024>>>();
    scatter_kernel<<<(N + 255) / 256, 256>>>(verts, N);
    knn_binned_kernel<<<1024, 256>>>(gverts, M);
    f1tab_kernel<<<1036, 256>>>(feats, verts, ew1, eb1, gfeat, ow1, N);
    mlp_kernel<<<(M + WPB*GPW - 1) / (WPB*GPW), WPB * 32>>>(
        gverts, ew1,
        eg1, ebt1, ew2, eb2,
        ow1, ob1, og1, obt1, ow2, ob2,
        (float*)d_out, M);
}